// round 5
// baseline (speedup 1.0000x reference)
#include <cuda_runtime.h>
#include <cstdint>

#define POOL 7
#define NUM_ROIS 512
#define IMG_W 128
#define CH 1024
#define N_CELLS (NUM_ROIS * POOL * POOL)   // 25088
#define F4_PER_CELL (CH / 4)               // 256

// Precomputed per-cell params: corner offsets (in float4 units) + bilinear weights.
__device__ int4   g_offs[N_CELLS];
__device__ float4 g_wts[N_CELLS];

// ---------------- setup: one thread per cell ----------------
__global__ void roi_setup_kernel(const int* __restrict__ rois) {
    const int cell = blockIdx.x * blockDim.x + threadIdx.x;
    if (cell >= N_CELLS) return;

    const int roi = cell / (POOL * POOL);
    const int rem = cell - roi * (POOL * POOL);
    const int py  = rem / POOL;
    const int px  = rem - py * POOL;

    const int x = rois[roi * 4 + 0];
    const int y = rois[roi * 4 + 1];
    const int w = rois[roi * 4 + 2];
    const int h = rois[roi * 4 + 3];

    const float hf = (float)h;
    const float wf = (float)w;

    // half-pixel-center source coords, clamped (matches tf.image.resize bilinear)
    float ys = ((float)py + 0.5f) * hf * (1.0f / POOL) - 0.5f;
    float xs = ((float)px + 0.5f) * wf * (1.0f / POOL) - 0.5f;
    ys = fminf(fmaxf(ys, 0.0f), hf - 1.0f);
    xs = fminf(fmaxf(xs, 0.0f), wf - 1.0f);

    const int y0 = (int)floorf(ys);
    const int x0 = (int)floorf(xs);
    const int y1 = min(y0 + 1, h - 1);
    const int x1 = min(x0 + 1, w - 1);
    const float fy = ys - (float)y0;
    const float fx = xs - (float)x0;

    const int ay0 = y + y0, ay1 = y + y1;
    const int ax0 = x + x0, ax1 = x + x1;

    int4 off;
    off.x = (ay0 * IMG_W + ax0) * F4_PER_CELL;
    off.y = (ay0 * IMG_W + ax1) * F4_PER_CELL;
    off.z = (ay1 * IMG_W + ax0) * F4_PER_CELL;
    off.w = (ay1 * IMG_W + ax1) * F4_PER_CELL;
    g_offs[cell] = off;

    float4 wt;
    wt.x = (1.0f - fy) * (1.0f - fx);
    wt.y = (1.0f - fy) * fx;
    wt.z = fy * (1.0f - fx);
    wt.w = fy * fx;
    g_wts[cell] = wt;
}

// ---------------- main: 4 cells per 256-thread block ----------------
// 64 threads per cell; thread t covers f4 lanes t, t+64, t+128, t+192.
// __launch_bounds__(256, 2) => up to 128 regs/thread, so ALL 16 LDG.128
// payloads (64 regs) can be live at once: real MLP_eff ~16, not ~5.
__global__ __launch_bounds__(256, 2)
void roi_pool_kernel(const float* __restrict__ img,
                     float* __restrict__ out) {
    const int grp  = threadIdx.x >> 6;          // 0..3
    const int t    = threadIdx.x & 63;          // 0..63
    const int cell = blockIdx.x * 4 + grp;

    const int4   off = g_offs[cell];
    const float4 wt  = g_wts[cell];

    const float4* __restrict__ base = (const float4*)img;
    const float4* p00 = base + off.x + t;
    const float4* p01 = base + off.y + t;
    const float4* p10 = base + off.z + t;
    const float4* p11 = base + off.w + t;

    // Issue all 16 independent loads up front.
    float4 a0 = __ldg(p00 +   0), b0 = __ldg(p01 +   0), c0 = __ldg(p10 +   0), d0 = __ldg(p11 +   0);
    float4 a1 = __ldg(p00 +  64), b1 = __ldg(p01 +  64), c1 = __ldg(p10 +  64), d1 = __ldg(p11 +  64);
    float4 a2 = __ldg(p00 + 128), b2 = __ldg(p01 + 128), c2 = __ldg(p10 + 128), d2 = __ldg(p11 + 128);
    float4 a3 = __ldg(p00 + 192), b3 = __ldg(p01 + 192), c3 = __ldg(p10 + 192), d3 = __ldg(p11 + 192);

    float4* o = (float4*)out + (size_t)cell * F4_PER_CELL + t;

    float4 r;
    r.x = a0.x * wt.x + b0.x * wt.y + c0.x * wt.z + d0.x * wt.w;
    r.y = a0.y * wt.x + b0.y * wt.y + c0.y * wt.z + d0.y * wt.w;
    r.z = a0.z * wt.x + b0.z * wt.y + c0.z * wt.z + d0.z * wt.w;
    r.w = a0.w * wt.x + b0.w * wt.y + c0.w * wt.z + d0.w * wt.w;
    __stcs(o + 0, r);

    r.x = a1.x * wt.x + b1.x * wt.y + c1.x * wt.z + d1.x * wt.w;
    r.y = a1.y * wt.x + b1.y * wt.y + c1.y * wt.z + d1.y * wt.w;
    r.z = a1.z * wt.x + b1.z * wt.y + c1.z * wt.z + d1.z * wt.w;
    r.w = a1.w * wt.x + b1.w * wt.y + c1.w * wt.z + d1.w * wt.w;
    __stcs(o + 64, r);

    r.x = a2.x * wt.x + b2.x * wt.y + c2.x * wt.z + d2.x * wt.w;
    r.y = a2.y * wt.x + b2.y * wt.y + c2.y * wt.z + d2.y * wt.w;
    r.z = a2.z * wt.x + b2.z * wt.y + c2.z * wt.z + d2.z * wt.w;
    r.w = a2.w * wt.x + b2.w * wt.y + c2.w * wt.z + d2.w * wt.w;
    __stcs(o + 128, r);

    r.x = a3.x * wt.x + b3.x * wt.y + c3.x * wt.z + d3.x * wt.w;
    r.y = a3.y * wt.x + b3.y * wt.y + c3.y * wt.z + d3.y * wt.w;
    r.z = a3.z * wt.x + b3.z * wt.y + c3.z * wt.z + d3.z * wt.w;
    r.w = a3.w * wt.x + b3.w * wt.y + c3.w * wt.z + d3.w * wt.w;
    __stcs(o + 192, r);
}

extern "C" void kernel_launch(void* const* d_in, const int* in_sizes, int n_in,
                              void* d_out, int out_size) {
    const float* img  = (const float*)d_in[0];
    const int*   rois = (const int*)d_in[1];
    float*       out  = (float*)d_out;

    roi_setup_kernel<<<(N_CELLS + 255) / 256, 256>>>(rois);
    roi_pool_kernel<<<N_CELLS / 4, 256>>>(img, out);
}